// round 11
// baseline (speedup 1.0000x reference)
#include <cuda_runtime.h>
#include <cuda_bf16.h>
#include <cstdint>

// Embedding gather: out[token, :] = W[:, ids[token]], W row-major [D_MODEL, VOCAB].
// R11: 512B load requests. DRAM% was pinned ~62-67% across R7-R10 at all
// occupancies -> per-SM limit on outstanding 128B requests, not in-flight
// bytes. Odd VOCAB blocks aligned float4, so each row strip is loaded from
// its aligned-down base (LDG.128 legal) and the 0-3 element shift is applied
// when reading smem at distribute time. Tail cols (positions 128..130) come
// from a per-row 16B cp.async into a 4-deep side buffer (4-deep: 2-deep would
// race the previous chunk's distribute).

#define VOCAB     50257
#define D_MODEL   1024
#define N_TOK     (4 * 4096)
#define W_SIZE    ((long)D_MODEL * VOCAB)

#define TILE_C    128
#define TILE_BITS 7
#define N_TILES   ((VOCAB + TILE_C - 1) / TILE_C)   // 393
#define TILE_D    32
#define N_CHUNK   (D_MODEL / TILE_D)                // 32
#define PAD       132                               // multiple of 4: STS.128 aligned
#define STAGE_ELEMS (TILE_D * PAD)                  // 4224 floats
#define CAP       1024
#define NTHREADS  512

__device__ __forceinline__ void cp_async16(uint32_t saddr, const void* gptr) {
    asm volatile("cp.async.ca.shared.global [%0], [%1], 16;\n"
                 :: "r"(saddr), "l"(gptr));
}
__device__ __forceinline__ void cp_commit() {
    asm volatile("cp.async.commit_group;\n");
}
template <int N>
__device__ __forceinline__ void cp_wait() {
    asm volatile("cp.async.wait_group %0;\n" :: "n"(N));
}

__global__ __launch_bounds__(NTHREADS, 3)
void gather_tile_kernel(const int* __restrict__ ids,
                        const float* __restrict__ W,
                        float* __restrict__ out) {
    const int tile = blockIdx.x;

    __shared__ float buf[2][STAGE_ELEMS];       // 33.8 KB
    __shared__ float sextra[4][TILE_D][4];      // 2 KB: positions 128..131
    __shared__ int   s_list[CAP];               // 4 KB
    __shared__ int   s_cnt;

    const int tid  = threadIdx.x;
    const int lane = tid & 31;
    const int wid  = tid >> 5;                  // 16 warps
    const int c0   = tile * TILE_C;
    // Row-start shift: (R*VOCAB + c0) & 3 with VOCAB==1 (mod 4), R = c*32+row
    // -> (row + c0) & 3. At distribute, row == lane.
    const int shift_l = (lane + c0) & 3;

    // Each warp owns rows {2*wid, 2*wid+1} of every chunk.
    const int row0 = wid * 2;

    if (tid == 0) s_cnt = 0;

    // Main load: one LDG.128 per lane from the aligned-down strip base.
    auto load_main = [&](int c, int row) -> float4 {
        const long gstart = (long)(c * TILE_D + row) * VOCAB + c0;
        const long abase  = gstart & ~3L;
        const long idx    = abase + 4 * lane;
        if (idx + 4 <= W_SIZE)
            return *reinterpret_cast<const float4*>(W + idx);
        return make_float4(0.f, 0.f, 0.f, 0.f);
    };
    // Tail: strip elements 128..131 (16B-aligned) -> sextra[slot][row].
    auto issue_extra = [&](int c, int row, int slot) {
        if (lane == 0) {
            const long gstart = (long)(c * TILE_D + row) * VOCAB + c0;
            const long idx    = (gstart & ~3L) + 128;
            if (idx + 4 <= W_SIZE)
                cp_async16((uint32_t)__cvta_generic_to_shared(&sextra[slot][row][0]),
                           W + idx);
        }
    };

    float4 rcur0, rcur1, rnext0, rnext1;

    // Prologue: chunk-0 loads + extras; filter runs in their shadow.
    rcur0 = load_main(0, row0);
    rcur1 = load_main(0, row0 + 1);
    issue_extra(0, row0, 0);
    issue_extra(0, row0 + 1, 0);
    cp_commit();

    __syncthreads();   // s_cnt = 0 visible

    // Filter: find tokens whose id falls in this tile. Order irrelevant.
    const int4* __restrict__ ids4 = (const int4*)ids;
    for (int i = tid; i < N_TOK / 4; i += NTHREADS) {
        const int4 v = ids4[i];
        const int base_tok = i * 4;
        #pragma unroll
        for (int k = 0; k < 4; k++) {
            const int id = (&v.x)[k];
            if ((id >> TILE_BITS) == tile) {
                const int pos = atomicAdd(&s_cnt, 1);
                if (pos < CAP)
                    s_list[pos] = ((id & (TILE_C - 1)) << 16) | (base_tok + k);
            }
        }
    }
    __syncthreads();

    const int cnt = s_cnt;
    if (cnt == 0) { cp_wait<0>(); return; }    // uniform block exit
    const bool overflow = (cnt > CAP);
    const int n = overflow ? 0 : cnt;

    for (int c = 0; c < N_CHUNK; c++) {
        // Issue chunk c+1: main loads to regs, extras to sextra[(c+1)&3].
        // sextra slot safety: slot (c+1)&3 was last read at distribute(c-3),
        // which completed before barrier c-2 < this issue point.
        if (c + 1 < N_CHUNK) {
            rnext0 = load_main(c + 1, row0);
            rnext1 = load_main(c + 1, row0 + 1);
            issue_extra(c + 1, row0, (c + 1) & 3);
            issue_extra(c + 1, row0 + 1, (c + 1) & 3);
        }
        cp_commit();   // possibly-empty group keeps wait count valid

        // Stage chunk c mains: 2 x STS.128, 16B-aligned (PAD % 4 == 0).
        // buf[c&1] last distributed at iter c-2, separated by barrier c-1.
        float* sstage = &buf[c & 1][0];
        *reinterpret_cast<float4*>(&sstage[ row0      * PAD + 4 * lane]) = rcur0;
        *reinterpret_cast<float4*>(&sstage[(row0 + 1) * PAD + 4 * lane]) = rcur1;

        cp_wait<1>();    // chunk c extras (committed last iteration) landed
        __syncthreads();

        // Distribute chunk c: out[token, d0+lane] = strip position col+shift.
        const int d0 = c * TILE_D;
        for (int s = wid; s < n; s += 16) {
            const int pk    = s_list[s];
            const int col   = pk >> 16;
            const int token = pk & 0xFFFF;
            const int p     = col + shift_l;
            const float v = (p < TILE_C) ? sstage[lane * PAD + p]
                                         : sextra[c & 3][lane][p - TILE_C];
            out[(long)token * D_MODEL + d0 + lane] = v;
        }
        if (overflow) {
            // Correct-for-any-input fallback (never taken here; idempotent).
            for (int s = wid; s < N_TOK; s += 16) {
                const int id = __ldg(&ids[s]);
                if ((id >> TILE_BITS) == tile) {
                    const int p = (id & (TILE_C - 1)) + shift_l;
                    const float v = (p < TILE_C) ? sstage[lane * PAD + p]
                                                 : sextra[c & 3][lane][p - TILE_C];
                    out[(long)s * D_MODEL + d0 + lane] = v;
                }
            }
        }

        rcur0 = rnext0;
        rcur1 = rnext1;
    }
    cp_wait<0>();
}

extern "C" void kernel_launch(void* const* d_in, const int* in_sizes, int n_in,
                              void* d_out, int out_size) {
    const int* ids = nullptr;
    const float* W = nullptr;
    for (int i = 0; i < n_in; i++) {
        if (in_sizes[i] == N_TOK) ids = (const int*)d_in[i];
        else if (in_sizes[i] == D_MODEL * VOCAB) W = (const float*)d_in[i];
    }
    float* out = (float*)d_out;

    gather_tile_kernel<<<N_TILES, NTHREADS>>>(ids, W, out);
}